// round 3
// baseline (speedup 1.0000x reference)
#include <cuda_runtime.h>
#include <math.h>

#define BB 32
#define SS 4096
#define HH 256
#define DD 512
#define MM (BB*SS)

// ---- scratch (device globals; no allocation allowed) ----
__device__ float g_decf[BB*DD];        // dec_feat (B,D)
__device__ float g_score[MM];          // raw scores (B,S)
__device__ float g_ctx_part[8*BB*DD];  // split-S context partials

__device__ __forceinline__ unsigned f2tf32(float x) {
    unsigned u;
    asm("cvt.rna.tf32.f32 %0, %1;" : "=r"(u) : "f"(x));
    return u;
}

__device__ __forceinline__ void mma_tf32(float c[4], const unsigned a[4], const unsigned b[2]) {
    asm volatile(
        "mma.sync.aligned.m16n8k8.row.col.f32.tf32.tf32.f32 "
        "{%0,%1,%2,%3},{%4,%5,%6,%7},{%8,%9},{%0,%1,%2,%3};"
        : "+f"(c[0]), "+f"(c[1]), "+f"(c[2]), "+f"(c[3])
        : "r"(a[0]), "r"(a[1]), "r"(a[2]), "r"(a[3]), "r"(b[0]), "r"(b[1]));
}

// ============================================================
// K0: dec_feat[b,n] = sum_k s_t[b,k]*Ws[n,k] + Ws_b[n]
//     s_t = concat(h_dec[b], c_dec[b])
// grid (B, 4), 128 threads
// ============================================================
__global__ void __launch_bounds__(128) decfeat_kernel(
    const float* __restrict__ h, const float* __restrict__ c,
    const float* __restrict__ Ws, const float* __restrict__ Wsb)
{
    int b = blockIdx.x;
    int n = blockIdx.y * 128 + threadIdx.x;
    __shared__ float st[DD];
    for (int p = threadIdx.x; p < DD; p += 128)
        st[p] = (p < HH) ? h[b*HH + p] : c[b*HH + (p - HH)];
    __syncthreads();
    float acc = Wsb[n];
    const float4* wrow = (const float4*)(Ws + (size_t)n * DD);
#pragma unroll 8
    for (int k4 = 0; k4 < DD/4; ++k4) {
        float4 w = wrow[k4];
        acc += w.x * st[k4*4+0] + w.y * st[k4*4+1]
             + w.z * st[k4*4+2] + w.w * st[k4*4+3];
    }
    g_decf[b*DD + n] = acc;
}

// ============================================================
// K1: fused score GEMM.
// CTA: 64 rows of encoder resident in smem (tf32), loops 8 n-tiles
// of 64, k streamed in 64-chunks of Wh. Epilogue fuses
// tanh(q + dec_feat + cov*wc) * v and reduces over n into score.
// grid 2048, 256 threads, dyn smem 156160 B
// ============================================================
#define SE_STRIDE 516   // 512 + 4 pad
#define SW_STRIDE 68    // 64 + 4 pad

__global__ void __launch_bounds__(256) score_kernel(
    const float* __restrict__ enc, const float* __restrict__ Wh,
    const float* __restrict__ cov, const float* __restrict__ wc,
    const float* __restrict__ vw)
{
    extern __shared__ float sm[];
    float* sE     = sm;                     // [64][516] tf32 bits
    float* sW     = sE + 64*SE_STRIDE;      // [64][68]  tf32 bits
    float* sDecf  = sW + 64*SW_STRIDE;      // [512]
    float* sWc    = sDecf + DD;             // [512]
    float* sV     = sWc + DD;               // [512]
    float* sCov   = sV + DD;                // [64]
    float* sScore = sCov + 64;              // [64]

    const int tid  = threadIdx.x;
    const int row0 = blockIdx.x * 64;
    const int b    = row0 >> 12;            // /4096

    // Load encoder slab (64 x 512) -> tf32 in sE
    for (int i = tid; i < 64*128; i += 256) {
        int r = i >> 7, c4 = i & 127;
        float4 v = *(const float4*)(enc + (size_t)(row0 + r)*DD + c4*4);
        unsigned* dst = (unsigned*)(sE + r*SE_STRIDE + c4*4);
        dst[0] = f2tf32(v.x); dst[1] = f2tf32(v.y);
        dst[2] = f2tf32(v.z); dst[3] = f2tf32(v.w);
    }
    for (int i = tid; i < DD; i += 256) {
        sDecf[i] = g_decf[b*DD + i];
        sWc[i]   = wc[i];
        sV[i]    = vw[i];
    }
    if (tid < 64) { sCov[tid] = cov[row0 + tid]; sScore[tid] = 0.f; }
    __syncthreads();

    const int lane = tid & 31, wid = tid >> 5;
    const int warpM = wid & 1;      // 0..1 -> 32 rows each
    const int warpN = wid >> 1;     // 0..3 -> 16 cols each (within 64 n-tile)
    const int g = lane >> 2, q = lane & 3;

    float rs0 = 0.f, rs1 = 0.f, rs2 = 0.f, rs3 = 0.f;

    for (int nt = 0; nt < 8; ++nt) {
        float acc[2][2][4];
#pragma unroll
        for (int mi = 0; mi < 2; ++mi)
#pragma unroll
            for (int ni = 0; ni < 2; ++ni)
#pragma unroll
                for (int j = 0; j < 4; ++j) acc[mi][ni][j] = 0.f;

        for (int ko = 0; ko < 8; ++ko) {
            __syncthreads();
            // load Wh tile [64 n][64 k] -> tf32 in sW
            for (int i = tid; i < 64*16; i += 256) {
                int r = i >> 4, c4 = i & 15;
                float4 v = *(const float4*)(Wh + (size_t)(nt*64 + r)*DD + ko*64 + c4*4);
                unsigned* dst = (unsigned*)(sW + r*SW_STRIDE + c4*4);
                dst[0] = f2tf32(v.x); dst[1] = f2tf32(v.y);
                dst[2] = f2tf32(v.z); dst[3] = f2tf32(v.w);
            }
            __syncthreads();

            const unsigned* pe = (const unsigned*)sE;
            const unsigned* pw = (const unsigned*)sW;
#pragma unroll
            for (int ks = 0; ks < 8; ++ks) {
                const int kc = ko*64 + ks*8;
                unsigned a[2][4], bf[2][2];
#pragma unroll
                for (int mi = 0; mi < 2; ++mi) {
                    int rb = warpM*32 + mi*16 + g;
                    a[mi][0] = pe[(size_t)rb      *SE_STRIDE + kc + q];
                    a[mi][1] = pe[(size_t)(rb + 8)*SE_STRIDE + kc + q];
                    a[mi][2] = pe[(size_t)rb      *SE_STRIDE + kc + 4 + q];
                    a[mi][3] = pe[(size_t)(rb + 8)*SE_STRIDE + kc + 4 + q];
                }
#pragma unroll
                for (int ni = 0; ni < 2; ++ni) {
                    int nb = warpN*16 + ni*8 + g;
                    bf[ni][0] = pw[nb*SW_STRIDE + ks*8 + q];
                    bf[ni][1] = pw[nb*SW_STRIDE + ks*8 + 4 + q];
                }
#pragma unroll
                for (int mi = 0; mi < 2; ++mi)
#pragma unroll
                    for (int ni = 0; ni < 2; ++ni)
                        mma_tf32(acc[mi][ni], a[mi], bf[ni]);
            }
        }

        // epilogue: t = tanh(q + decf + cov*wc) * v, reduce over n
#pragma unroll
        for (int mi = 0; mi < 2; ++mi) {
            int r0 = warpM*32 + mi*16 + g;
            float cv0 = sCov[r0], cv1 = sCov[r0 + 8];
#pragma unroll
            for (int ni = 0; ni < 2; ++ni) {
                int cbase = nt*64 + warpN*16 + ni*8 + q*2;
#pragma unroll
                for (int cc = 0; cc < 2; ++cc) {
                    int cidx = cbase + cc;
                    float dfc = sDecf[cidx], wcc = sWc[cidx], vc = sV[cidx];
                    float t0 = tanhf(acc[mi][ni][cc]     + dfc + cv0*wcc) * vc;
                    float t1 = tanhf(acc[mi][ni][2 + cc] + dfc + cv1*wcc) * vc;
                    if (mi == 0) { rs0 += t0; rs1 += t1; }
                    else         { rs2 += t0; rs3 += t1; }
                }
            }
        }
    }

    // reduce over the 4 column-lanes sharing a row
    rs0 += __shfl_xor_sync(0xffffffffu, rs0, 1); rs0 += __shfl_xor_sync(0xffffffffu, rs0, 2);
    rs1 += __shfl_xor_sync(0xffffffffu, rs1, 1); rs1 += __shfl_xor_sync(0xffffffffu, rs1, 2);
    rs2 += __shfl_xor_sync(0xffffffffu, rs2, 1); rs2 += __shfl_xor_sync(0xffffffffu, rs2, 2);
    rs3 += __shfl_xor_sync(0xffffffffu, rs3, 1); rs3 += __shfl_xor_sync(0xffffffffu, rs3, 2);
    if (q == 0) {
        atomicAdd(&sScore[warpM*32 +  0 + g], rs0);
        atomicAdd(&sScore[warpM*32 +  8 + g], rs1);
        atomicAdd(&sScore[warpM*32 + 16 + g], rs2);
        atomicAdd(&sScore[warpM*32 + 24 + g], rs3);
    }
    __syncthreads();
    if (tid < 64) g_score[row0 + tid] = sScore[tid];
}

// ============================================================
// K2: masked softmax + renormalize + coverage update, per batch.
// attn_i = exp(s_i - max)*m_i / sum_j exp(s_j - max)*m_j
// grid 32, 256 threads
// ============================================================
__global__ void __launch_bounds__(256) softmax_kernel(
    const float* __restrict__ mask, const float* __restrict__ cov,
    float* __restrict__ attn_out, float* __restrict__ covnew_out)
{
    int b = blockIdx.x, tid = threadIdx.x;
    __shared__ float red[256];
    float loc[16];
    float mx = -1e30f;
#pragma unroll
    for (int i = 0; i < 16; ++i) {
        loc[i] = g_score[b*SS + tid + i*256];
        mx = fmaxf(mx, loc[i]);
    }
    red[tid] = mx; __syncthreads();
    for (int o = 128; o > 0; o >>= 1) {
        if (tid < o) red[tid] = fmaxf(red[tid], red[tid + o]);
        __syncthreads();
    }
    mx = red[0]; __syncthreads();

    float sum = 0.f;
#pragma unroll
    for (int i = 0; i < 16; ++i) {
        loc[i] = expf(loc[i] - mx) * mask[b*SS + tid + i*256];
        sum += loc[i];
    }
    red[tid] = sum; __syncthreads();
    for (int o = 128; o > 0; o >>= 1) {
        if (tid < o) red[tid] += red[tid + o];
        __syncthreads();
    }
    float inv = 1.f / red[0];
#pragma unroll
    for (int i = 0; i < 16; ++i) {
        int idx = b*SS + tid + i*256;
        float a = loc[i] * inv;
        attn_out[idx]   = a;
        covnew_out[idx] = cov[idx] + a;
    }
}

// ============================================================
// K3: context partials. grid (8 s-chunks, B), 512 threads.
// Each CTA: 512 seq rows, 4 rows in flight, 128 d-threads (float4).
// ============================================================
__global__ void __launch_bounds__(512) context_kernel(
    const float* __restrict__ enc, const float* __restrict__ attn)
{
    int chunk = blockIdx.x, b = blockIdx.y, tid = threadIdx.x;
    __shared__ float sAttn[512];
    __shared__ float4 red4[512];
    sAttn[tid & 511] = attn[b*SS + chunk*512 + (tid & 511)];
    __syncthreads();
    int dt = tid & 127, sg = tid >> 7;
    float4 acc = make_float4(0.f, 0.f, 0.f, 0.f);
#pragma unroll 4
    for (int s = sg; s < 512; s += 4) {
        float a = sAttn[s];
        float4 e = *(const float4*)(enc + (size_t)(b*SS + chunk*512 + s)*DD + dt*4);
        acc.x += a*e.x; acc.y += a*e.y; acc.z += a*e.z; acc.w += a*e.w;
    }
    red4[tid] = acc; __syncthreads();
    if (sg == 0) {
        float4 r = red4[dt], r1 = red4[128+dt], r2 = red4[256+dt], r3 = red4[384+dt];
        r.x += r1.x + r2.x + r3.x; r.y += r1.y + r2.y + r3.y;
        r.z += r1.z + r2.z + r3.z; r.w += r1.w + r2.w + r3.w;
        *(float4*)(&g_ctx_part[((size_t)chunk*BB + b)*DD + dt*4]) = r;
    }
}

// K4: reduce the 8 s-chunk partials -> context output (deterministic)
__global__ void __launch_bounds__(1024) ctx_reduce_kernel(float* __restrict__ out_ctx)
{
    int i = blockIdx.x * 1024 + threadIdx.x;  // 0..16383
    float s = 0.f;
#pragma unroll
    for (int c = 0; c < 8; ++c) s += g_ctx_part[c*(BB*DD) + i];
    out_ctx[i] = s;
}

// ============================================================
extern "C" void kernel_launch(void* const* d_in, const int* in_sizes, int n_in,
                              void* d_out, int out_size)
{
    const float* enc  = (const float*)d_in[0];
    const float* h    = (const float*)d_in[1];
    const float* c    = (const float*)d_in[2];
    const float* mask = (const float*)d_in[3];
    const float* cov  = (const float*)d_in[4];
    const float* Wh   = (const float*)d_in[5];
    const float* Ws   = (const float*)d_in[6];
    const float* Wsb  = (const float*)d_in[7];
    const float* wc   = (const float*)d_in[8];
    const float* vw   = (const float*)d_in[9];

    float* out      = (float*)d_out;
    float* out_ctx  = out;                 // (B,D)   16384
    float* out_attn = out + BB*DD;         // (B,S)   131072
    float* out_cov  = out_attn + BB*SS;    // (B,S)   131072

    const int SCORE_SMEM = (64*SE_STRIDE + 64*SW_STRIDE + 3*DD + 128) * 4;
    cudaFuncSetAttribute(score_kernel, cudaFuncAttributeMaxDynamicSharedMemorySize, SCORE_SMEM);

    decfeat_kernel<<<dim3(BB, 4), 128>>>(h, c, Ws, Wsb);
    score_kernel<<<MM/64, 256, SCORE_SMEM>>>(enc, Wh, cov, wc, vw);
    softmax_kernel<<<BB, 256>>>(mask, cov, out_attn, out_cov);
    context_kernel<<<dim3(8, BB), 512>>>(enc, out_attn);
    ctx_reduce_kernel<<<(BB*DD)/1024, 1024>>>(out_ctx);
}

// round 5
// speedup vs baseline: 5.1135x; 5.1135x over previous
#include <cuda_runtime.h>
#include <cuda_bf16.h>
#include <math.h>
#include <stdint.h>

#define BB 32
#define SS 4096
#define HH 256
#define DD 512
#define MM (BB*SS)

// ---- scratch (device globals; no allocation allowed) ----
__device__ float g_decf[BB*DD];                 // dec_feat (B,D)
__device__ float g_score[MM];                   // raw scores (B,S)
__device__ float g_ctx_part[8*BB*DD];           // split-S context partials
__device__ __nv_bfloat16 g_WhBf[DD*DD];         // Wh pre-converted to bf16

// ============================================================
// helpers
// ============================================================
__device__ __forceinline__ uint32_t smem_to_u32(const void* p) {
    uint32_t a;
    asm("{ .reg .u64 t; cvta.to.shared.u64 t, %1; cvt.u32.u64 %0, t; }" : "=r"(a) : "l"(p));
    return a;
}

#define CP_ASYNC16(dst, src) \
    asm volatile("cp.async.cg.shared.global [%0], [%1], 16;" :: "r"(dst), "l"(src) : "memory")
#define CP_COMMIT() asm volatile("cp.async.commit_group;" ::: "memory")
#define CP_WAIT(n)  asm volatile("cp.async.wait_group %0;" :: "n"(n) : "memory")

__device__ __forceinline__ void ldsm_x4(uint32_t r[4], uint32_t addr) {
    asm volatile("ldmatrix.sync.aligned.m8n8.x4.shared.b16 {%0,%1,%2,%3}, [%4];"
        : "=r"(r[0]), "=r"(r[1]), "=r"(r[2]), "=r"(r[3]) : "r"(addr));
}

__device__ __forceinline__ void mma_bf16(float c[4], const uint32_t a[4], const uint32_t* b) {
    asm volatile(
        "mma.sync.aligned.m16n8k16.row.col.f32.bf16.bf16.f32 "
        "{%0,%1,%2,%3},{%4,%5,%6,%7},{%8,%9},{%0,%1,%2,%3};"
        : "+f"(c[0]), "+f"(c[1]), "+f"(c[2]), "+f"(c[3])
        : "r"(a[0]), "r"(a[1]), "r"(a[2]), "r"(a[3]), "r"(b[0]), "r"(b[1]));
}

__device__ __forceinline__ uint4 pack8bf16(float4 a, float4 b) {
    __nv_bfloat162 p0 = __floats2bfloat162_rn(a.x, a.y);
    __nv_bfloat162 p1 = __floats2bfloat162_rn(a.z, a.w);
    __nv_bfloat162 p2 = __floats2bfloat162_rn(b.x, b.y);
    __nv_bfloat162 p3 = __floats2bfloat162_rn(b.z, b.w);
    uint4 r;
    r.x = *(uint32_t*)&p0; r.y = *(uint32_t*)&p1;
    r.z = *(uint32_t*)&p2; r.w = *(uint32_t*)&p3;
    return r;
}

// SMEM layout (bytes)
// sA: 128 rows x 512 bf16 (1024 B/row, XOR-swizzled 16B chunks)   131072
// sW: 2 x (128 n-rows x 128 bf16 = 256 B/row, swizzled)            65536
// params: decf/wc/v [512]f each, cov[128]f, score[128]f             7168
#define SM_A    0
#define SM_W    131072
#define SM_PAR  196608
#define SM_TOTAL 203776

// ============================================================
// K-1: pre-convert Wh (512x512 f32) -> bf16, row-major [n][k]
// ============================================================
__global__ void __launch_bounds__(256) convert_wh_kernel(const float* __restrict__ Wh)
{
    int i = (blockIdx.x * 256 + threadIdx.x) * 8;   // 8 elems/thread, grid 128
    float4 v0 = *(const float4*)(Wh + i);
    float4 v1 = *(const float4*)(Wh + i + 4);
    *(uint4*)((char*)g_WhBf + (size_t)i * 2) = pack8bf16(v0, v1);
}

// ============================================================
// K0: dec_feat[b,n] = sum_k s_t[b,k]*Ws[n,k] + Ws_b[n]
// ============================================================
__global__ void __launch_bounds__(128) decfeat_kernel(
    const float* __restrict__ h, const float* __restrict__ c,
    const float* __restrict__ Ws, const float* __restrict__ Wsb)
{
    int b = blockIdx.x;
    int n = blockIdx.y * 128 + threadIdx.x;
    __shared__ float st[DD];
    for (int p = threadIdx.x; p < DD; p += 128)
        st[p] = (p < HH) ? h[b*HH + p] : c[b*HH + (p - HH)];
    __syncthreads();
    float acc = Wsb[n];
    const float4* wrow = (const float4*)(Ws + (size_t)n * DD);
#pragma unroll 8
    for (int k4 = 0; k4 < DD/4; ++k4) {
        float4 w = wrow[k4];
        acc += w.x * st[k4*4+0] + w.y * st[k4*4+1]
             + w.z * st[k4*4+2] + w.w * st[k4*4+3];
    }
    g_decf[b*DD + n] = acc;
}

// ============================================================
// K1: fused score GEMM, bf16 mma.sync.m16n8k16 + ldmatrix + cp.async.
// CTA: 128 enc rows resident in smem (bf16), N=512 in 4 n-tiles of 128,
// K=512 per n-tile in 4 chunks of 128 (cp.async double-buffered Wh).
// Warp grid 2(M)x4(N): warp tile 64 rows x 32 cols.
// Epilogue fuses tanh.approx(q + decf + cov*wc) * v, reduced over n.
// grid 1024, 256 threads
// ============================================================
__global__ void __launch_bounds__(256) score_bf16_kernel(
    const float* __restrict__ enc, const float* __restrict__ cov,
    const float* __restrict__ wc, const float* __restrict__ vw)
{
    extern __shared__ __align__(1024) char smem[];
    const uint32_t sbase = smem_to_u32(smem);
    const int tid = threadIdx.x;
    const int lane = tid & 31, wid = tid >> 5;
    const int warpM = wid >> 2, warpN = wid & 3;
    const int g = lane >> 2, q = lane & 3;
    const int row0 = blockIdx.x * 128;
    const int b = row0 >> 12;

    float* sDecf  = (float*)(smem + SM_PAR);
    float* sWc    = sDecf + 512;
    float* sV     = sWc + 512;
    float* sCov   = sV + 512;
    float* sScore = sCov + 128;

    // --- prefetch W tile (nt=0,kc=0) into buffer 0 ---
    {
        const char* src = (const char*)(g_WhBf);           // nt=0,kc=0 origin
#pragma unroll
        for (int i = 0; i < 8; ++i) {
            int cix = tid + i * 256;                        // 0..2047 16B chunks
            int n = cix >> 4, ch = cix & 15;
            uint32_t dst = sbase + SM_W + n*256 + (((uint32_t)(ch ^ (n & 7))) << 4);
            CP_ASYNC16(dst, src + ((size_t)n*DD + ch*8) * 2);
        }
        CP_COMMIT();
    }

    // --- load A slab: 128 rows x 512 f32 -> bf16, swizzled ---
#pragma unroll
    for (int i = 0; i < 32; ++i) {
        int cix = tid + i * 256;                            // 0..8191 chunks
        int row = cix >> 6, ch = cix & 63;
        const float4* src = (const float4*)(enc + (size_t)(row0 + row)*DD + ch*8);
        uint4 v = pack8bf16(src[0], src[1]);
        *(uint4*)(smem + SM_A + row*1024 + (((uint32_t)(ch ^ (row & 7))) << 4)) = v;
    }
    // --- params ---
    for (int i = tid; i < 512; i += 256) {
        sDecf[i] = g_decf[b*DD + i];
        sWc[i]   = wc[i];
        sV[i]    = vw[i];
    }
    if (tid < 128) { sCov[tid] = cov[row0 + tid]; sScore[tid] = 0.f; }
    __syncthreads();

    float rs[4][2];
#pragma unroll
    for (int mi = 0; mi < 4; ++mi) { rs[mi][0] = 0.f; rs[mi][1] = 0.f; }

    // hoisted lane-dependent pieces
    const int aLaneRow = lane & 15;          // row within m16 tile
    const int aChunkOff = lane >> 4;         // 0/1: k 16B chunk select
    const int bLaneRowOff = ((lane & 16) ? 8 : 0) + (lane & 7);
    const int bChunkOff = (lane >> 3) & 1;

    for (int nt = 0; nt < 4; ++nt) {
        float acc[4][4][4];
#pragma unroll
        for (int mi = 0; mi < 4; ++mi)
#pragma unroll
            for (int ni = 0; ni < 4; ++ni)
#pragma unroll
                for (int j = 0; j < 4; ++j) acc[mi][ni][j] = 0.f;

        for (int kc = 0; kc < 4; ++kc) {
            const int idx = nt*4 + kc;
            // prefetch next W tile into the other buffer
            if (idx < 15) {
                const int nx = idx + 1;
                const int nt2 = nx >> 2, kc2 = nx & 3, buf2 = nx & 1;
                const char* src = (const char*)(g_WhBf + (size_t)(nt2*128)*DD + kc2*128);
#pragma unroll
                for (int i = 0; i < 8; ++i) {
                    int cix = tid + i * 256;
                    int n = cix >> 4, ch = cix & 15;
                    uint32_t dst = sbase + SM_W + buf2*32768 + n*256
                                 + (((uint32_t)(ch ^ (n & 7))) << 4);
                    CP_ASYNC16(dst, src + ((size_t)n*DD + ch*8) * 2);
                }
                CP_COMMIT();
                CP_WAIT(1);
            } else {
                CP_WAIT(0);
            }
            __syncthreads();

            const uint32_t wBase = sbase + SM_W + (idx & 1)*32768;

#pragma unroll
            for (int k16 = 0; k16 < 8; ++k16) {
                const int ck  = kc*16 + k16*2;   // A chunk idx (of 64)
                const int ck2 = k16*2;           // W chunk idx (of 16)

                uint32_t a[4][4];
#pragma unroll
                for (int mi = 0; mi < 4; ++mi) {
                    int row = warpM*64 + mi*16 + aLaneRow;
                    uint32_t addr = sbase + SM_A + row*1024
                                  + (((uint32_t)((ck + aChunkOff) ^ (row & 7))) << 4);
                    ldsm_x4(a[mi], addr);
                }
                uint32_t bf[2][4];
#pragma unroll
                for (int nj = 0; nj < 2; ++nj) {
                    int nrow = warpN*32 + nj*16 + bLaneRowOff;
                    uint32_t addr = wBase + nrow*256
                                  + (((uint32_t)((ck2 + bChunkOff) ^ (nrow & 7))) << 4);
                    ldsm_x4(bf[nj], addr);
                }
#pragma unroll
                for (int mi = 0; mi < 4; ++mi)
#pragma unroll
                    for (int ni = 0; ni < 4; ++ni)
                        mma_bf16(acc[mi][ni], a[mi], &bf[ni >> 1][(ni & 1) * 2]);
            }
            __syncthreads();
        }

        // epilogue for this n-tile: tanh.approx(q + decf + cov*wc) * v
        const int colbase = nt*128 + warpN*32;
#pragma unroll
        for (int mi = 0; mi < 4; ++mi) {
            const int rowg = warpM*64 + mi*16 + g;
            const float cv0 = sCov[rowg], cv1 = sCov[rowg + 8];
#pragma unroll
            for (int ni = 0; ni < 4; ++ni) {
#pragma unroll
                for (int half = 0; half < 2; ++half) {
#pragma unroll
                    for (int jj = 0; jj < 2; ++jj) {
                        const int col = colbase + ni*8 + q*2 + jj;
                        float arg = acc[mi][ni][half*2 + jj]
                                  + sDecf[col] + (half ? cv1 : cv0) * sWc[col];
                        float t;
                        asm("tanh.approx.f32 %0, %1;" : "=f"(t) : "f"(arg));
                        rs[mi][half] += t * sV[col];
                    }
                }
            }
        }
    }

    // reduce over the 4 column-lanes (q) sharing each row, then across warpN
#pragma unroll
    for (int mi = 0; mi < 4; ++mi)
#pragma unroll
        for (int half = 0; half < 2; ++half) {
            float v = rs[mi][half];
            v += __shfl_xor_sync(0xffffffffu, v, 1);
            v += __shfl_xor_sync(0xffffffffu, v, 2);
            if (q == 0)
                atomicAdd(&sScore[warpM*64 + mi*16 + half*8 + g], v);
        }
    __syncthreads();
    if (tid < 128) g_score[row0 + tid] = sScore[tid];
}

// ============================================================
// K2: masked softmax + renormalize + coverage update, per batch.
// ============================================================
__global__ void __launch_bounds__(256) softmax_kernel(
    const float* __restrict__ mask, const float* __restrict__ cov,
    float* __restrict__ attn_out, float* __restrict__ covnew_out)
{
    int b = blockIdx.x, tid = threadIdx.x;
    __shared__ float red[256];
    float loc[16];
    float mx = -1e30f;
#pragma unroll
    for (int i = 0; i < 16; ++i) {
        loc[i] = g_score[b*SS + tid + i*256];
        mx = fmaxf(mx, loc[i]);
    }
    red[tid] = mx; __syncthreads();
    for (int o = 128; o > 0; o >>= 1) {
        if (tid < o) red[tid] = fmaxf(red[tid], red[tid + o]);
        __syncthreads();
    }
    mx = red[0]; __syncthreads();

    float sum = 0.f;
#pragma unroll
    for (int i = 0; i < 16; ++i) {
        loc[i] = expf(loc[i] - mx) * mask[b*SS + tid + i*256];
        sum += loc[i];
    }
    red[tid] = sum; __syncthreads();
    for (int o = 128; o > 0; o >>= 1) {
        if (tid < o) red[tid] += red[tid + o];
        __syncthreads();
    }
    float inv = 1.f / red[0];
#pragma unroll
    for (int i = 0; i < 16; ++i) {
        int idx = b*SS + tid + i*256;
        float a = loc[i] * inv;
        attn_out[idx]   = a;
        covnew_out[idx] = cov[idx] + a;
    }
}

// ============================================================
// K3: context partials. grid (8 s-chunks, B), 512 threads.
// ============================================================
__global__ void __launch_bounds__(512) context_kernel(
    const float* __restrict__ enc, const float* __restrict__ attn)
{
    int chunk = blockIdx.x, b = blockIdx.y, tid = threadIdx.x;
    __shared__ float sAttn[512];
    __shared__ float4 red4[512];
    sAttn[tid & 511] = attn[b*SS + chunk*512 + (tid & 511)];
    __syncthreads();
    int dt = tid & 127, sg = tid >> 7;
    float4 acc = make_float4(0.f, 0.f, 0.f, 0.f);
#pragma unroll 4
    for (int s = sg; s < 512; s += 4) {
        float a = sAttn[s];
        float4 e = *(const float4*)(enc + (size_t)(b*SS + chunk*512 + s)*DD + dt*4);
        acc.x += a*e.x; acc.y += a*e.y; acc.z += a*e.z; acc.w += a*e.w;
    }
    red4[tid] = acc; __syncthreads();
    if (sg == 0) {
        float4 r = red4[dt], r1 = red4[128+dt], r2 = red4[256+dt], r3 = red4[384+dt];
        r.x += r1.x + r2.x + r3.x; r.y += r1.y + r2.y + r3.y;
        r.z += r1.z + r2.z + r3.z; r.w += r1.w + r2.w + r3.w;
        *(float4*)(&g_ctx_part[((size_t)chunk*BB + b)*DD + dt*4]) = r;
    }
}

// K4: reduce the 8 s-chunk partials -> context output (deterministic)
__global__ void __launch_bounds__(1024) ctx_reduce_kernel(float* __restrict__ out_ctx)
{
    int i = blockIdx.x * 1024 + threadIdx.x;  // 0..16383
    float s = 0.f;
#pragma unroll
    for (int c = 0; c < 8; ++c) s += g_ctx_part[c*(BB*DD) + i];
    out_ctx[i] = s;
}

// ============================================================
extern "C" void kernel_launch(void* const* d_in, const int* in_sizes, int n_in,
                              void* d_out, int out_size)
{
    const float* enc  = (const float*)d_in[0];
    const float* h    = (const float*)d_in[1];
    const float* c    = (const float*)d_in[2];
    const float* mask = (const float*)d_in[3];
    const float* cov  = (const float*)d_in[4];
    const float* Wh   = (const float*)d_in[5];
    const float* Ws   = (const float*)d_in[6];
    const float* Wsb  = (const float*)d_in[7];
    const float* wc   = (const float*)d_in[8];
    const float* vw   = (const float*)d_in[9];

    float* out      = (float*)d_out;
    float* out_ctx  = out;                 // (B,D)   16384
    float* out_attn = out + BB*DD;         // (B,S)   131072
    float* out_cov  = out_attn + BB*SS;    // (B,S)   131072

    cudaFuncSetAttribute(score_bf16_kernel,
                         cudaFuncAttributeMaxDynamicSharedMemorySize, SM_TOTAL);

    convert_wh_kernel<<<DD*DD/(256*8), 256>>>(Wh);
    decfeat_kernel<<<dim3(BB, 4), 128>>>(h, c, Ws, Wsb);
    score_bf16_kernel<<<MM/128, 256, SM_TOTAL>>>(enc, cov, wc, vw);
    softmax_kernel<<<BB, 256>>>(mask, cov, out_attn, out_cov);
    context_kernel<<<dim3(8, BB), 512>>>(enc, out_attn);
    ctx_reduce_kernel<<<(BB*DD)/1024, 1024>>>(out_ctx);
}

// round 8
// speedup vs baseline: 5.1390x; 1.0050x over previous
#include <cuda_runtime.h>
#include <cuda_bf16.h>
#include <math.h>
#include <stdint.h>

#define BB 32
#define SS 4096
#define HH 256
#define DD 512
#define MM (BB*SS)

#define CTX_CHUNKS 16

// ---- scratch (device globals; no allocation allowed) ----
__device__ float g_decf[BB*DD];                 // dec_feat (B,D)
__device__ float g_score[MM];                   // raw scores (B,S)
__device__ float g_ctx_part[CTX_CHUNKS*BB*DD];  // split-S context partials
__device__ __nv_bfloat16 g_WhBf[DD*DD];         // Wh pre-converted to bf16

// ============================================================
// helpers
// ============================================================
__device__ __forceinline__ uint32_t smem_to_u32(const void* p) {
    uint32_t a;
    asm("{ .reg .u64 t; cvta.to.shared.u64 t, %1; cvt.u32.u64 %0, t; }" : "=r"(a) : "l"(p));
    return a;
}

#define CP_ASYNC16(dst, src) \
    asm volatile("cp.async.cg.shared.global [%0], [%1], 16;" :: "r"(dst), "l"(src) : "memory")
#define CP_COMMIT() asm volatile("cp.async.commit_group;" ::: "memory")
#define CP_WAIT(n)  asm volatile("cp.async.wait_group %0;" :: "n"(n) : "memory")

__device__ __forceinline__ void ldsm_x4(uint32_t r[4], uint32_t addr) {
    asm volatile("ldmatrix.sync.aligned.m8n8.x4.shared.b16 {%0,%1,%2,%3}, [%4];"
        : "=r"(r[0]), "=r"(r[1]), "=r"(r[2]), "=r"(r[3]) : "r"(addr));
}

__device__ __forceinline__ void mma_bf16(float c[4], const uint32_t a[4], const uint32_t* b) {
    asm volatile(
        "mma.sync.aligned.m16n8k16.row.col.f32.bf16.bf16.f32 "
        "{%0,%1,%2,%3},{%4,%5,%6,%7},{%8,%9},{%0,%1,%2,%3};"
        : "+f"(c[0]), "+f"(c[1]), "+f"(c[2]), "+f"(c[3])
        : "r"(a[0]), "r"(a[1]), "r"(a[2]), "r"(a[3]), "r"(b[0]), "r"(b[1]));
}

__device__ __forceinline__ uint4 pack8bf16(float4 a, float4 b) {
    __nv_bfloat162 p0 = __floats2bfloat162_rn(a.x, a.y);
    __nv_bfloat162 p1 = __floats2bfloat162_rn(a.z, a.w);
    __nv_bfloat162 p2 = __floats2bfloat162_rn(b.x, b.y);
    __nv_bfloat162 p3 = __floats2bfloat162_rn(b.z, b.w);
    uint4 r;
    r.x = *(uint32_t*)&p0; r.y = *(uint32_t*)&p1;
    r.z = *(uint32_t*)&p2; r.w = *(uint32_t*)&p3;
    return r;
}

// SMEM layout (bytes)
#define SM_A    0
#define SM_W    131072
#define SM_PAR  196608
#define SM_TOTAL 203776

// ============================================================
// K-1: pre-convert Wh (512x512 f32) -> bf16, row-major [n][k]
// ============================================================
__global__ void __launch_bounds__(256) convert_wh_kernel(const float* __restrict__ Wh)
{
    int i = (blockIdx.x * 256 + threadIdx.x) * 8;   // 8 elems/thread, grid 128
    float4 v0 = *(const float4*)(Wh + i);
    float4 v1 = *(const float4*)(Wh + i + 4);
    *(uint4*)((char*)g_WhBf + (size_t)i * 2) = pack8bf16(v0, v1);
}

// ============================================================
// K0: dec_feat[b,n] = sum_k s_t[b,k]*Ws[n,k] + Ws_b[n]
// ============================================================
__global__ void __launch_bounds__(128) decfeat_kernel(
    const float* __restrict__ h, const float* __restrict__ c,
    const float* __restrict__ Ws, const float* __restrict__ Wsb)
{
    int b = blockIdx.x;
    int n = blockIdx.y * 128 + threadIdx.x;
    __shared__ float st[DD];
    for (int p = threadIdx.x; p < DD; p += 128)
        st[p] = (p < HH) ? h[b*HH + p] : c[b*HH + (p - HH)];
    __syncthreads();
    float acc = Wsb[n];
    const float4* wrow = (const float4*)(Ws + (size_t)n * DD);
#pragma unroll 8
    for (int k4 = 0; k4 < DD/4; ++k4) {
        float4 w = wrow[k4];
        acc += w.x * st[k4*4+0] + w.y * st[k4*4+1]
             + w.z * st[k4*4+2] + w.w * st[k4*4+3];
    }
    g_decf[b*DD + n] = acc;
}

// ============================================================
// K1: fused score GEMM, bf16 mma.sync.m16n8k16 + ldmatrix + cp.async,
// with software-pipelined (double-buffered) register fragments.
// grid 1024, 256 threads
// ============================================================
__global__ void __launch_bounds__(256) score_bf16_kernel(
    const float* __restrict__ enc, const float* __restrict__ cov,
    const float* __restrict__ wc, const float* __restrict__ vw)
{
    extern __shared__ __align__(1024) char smem[];
    const uint32_t sbase = smem_to_u32(smem);
    const int tid = threadIdx.x;
    const int lane = tid & 31, wid = tid >> 5;
    const int warpM = wid >> 2, warpN = wid & 3;
    const int g = lane >> 2, q = lane & 3;
    const int row0 = blockIdx.x * 128;
    const int b = row0 >> 12;

    float* sDecf  = (float*)(smem + SM_PAR);
    float* sWc    = sDecf + 512;
    float* sV     = sWc + 512;
    float* sCov   = sV + 512;
    float* sScore = sCov + 128;

    // --- prefetch W tile (nt=0,kc=0) into buffer 0 ---
    {
        const char* src = (const char*)(g_WhBf);
#pragma unroll
        for (int i = 0; i < 8; ++i) {
            int cix = tid + i * 256;                        // 0..2047 16B chunks
            int n = cix >> 4, ch = cix & 15;
            uint32_t dst = sbase + SM_W + n*256 + (((uint32_t)(ch ^ (n & 7))) << 4);
            CP_ASYNC16(dst, src + ((size_t)n*DD + ch*8) * 2);
        }
        CP_COMMIT();
    }

    // --- load A slab: 128 rows x 512 f32 -> bf16, swizzled ---
#pragma unroll
    for (int i = 0; i < 32; ++i) {
        int cix = tid + i * 256;                            // 0..8191 chunks
        int row = cix >> 6, ch = cix & 63;
        const float4* src = (const float4*)(enc + (size_t)(row0 + row)*DD + ch*8);
        uint4 v = pack8bf16(src[0], src[1]);
        *(uint4*)(smem + SM_A + row*1024 + (((uint32_t)(ch ^ (row & 7))) << 4)) = v;
    }
    // --- params ---
    for (int i = tid; i < 512; i += 256) {
        sDecf[i] = g_decf[b*DD + i];
        sWc[i]   = wc[i];
        sV[i]    = vw[i];
    }
    if (tid < 128) { sCov[tid] = cov[row0 + tid]; sScore[tid] = 0.f; }
    __syncthreads();

    float rs[4][2];
#pragma unroll
    for (int mi = 0; mi < 4; ++mi) { rs[mi][0] = 0.f; rs[mi][1] = 0.f; }

    // hoisted lane-dependent pieces
    const int aLaneRow = lane & 15;
    const int aChunkOff = lane >> 4;
    const int bLaneRowOff = ((lane & 16) ? 8 : 0) + (lane & 7);
    const int bChunkOff = (lane >> 3) & 1;

    // precompute per-mi / per-nj base addresses (chunk XOR varies per k16)
    uint32_t aRowBase[4];
#pragma unroll
    for (int mi = 0; mi < 4; ++mi) {
        int row = warpM*64 + mi*16 + aLaneRow;
        aRowBase[mi] = sbase + SM_A + row*1024;
    }
    int aRowMask[4];
#pragma unroll
    for (int mi = 0; mi < 4; ++mi) aRowMask[mi] = (warpM*64 + mi*16 + aLaneRow) & 7;
    uint32_t bRowBase[2];
    int bRowMask[2];
#pragma unroll
    for (int nj = 0; nj < 2; ++nj) {
        int nrow = warpN*32 + nj*16 + bLaneRowOff;
        bRowBase[nj] = nrow*256;
        bRowMask[nj] = nrow & 7;
    }

    for (int nt = 0; nt < 4; ++nt) {
        float acc[4][4][4];
#pragma unroll
        for (int mi = 0; mi < 4; ++mi)
#pragma unroll
            for (int ni = 0; ni < 4; ++ni)
#pragma unroll
                for (int j = 0; j < 4; ++j) acc[mi][ni][j] = 0.f;

        for (int kc = 0; kc < 4; ++kc) {
            const int idx = nt*4 + kc;
            // prefetch next W tile into the other buffer
            if (idx < 15) {
                const int nx = idx + 1;
                const int nt2 = nx >> 2, kc2 = nx & 3, buf2 = nx & 1;
                const char* src = (const char*)(g_WhBf + (size_t)(nt2*128)*DD + kc2*128);
#pragma unroll
                for (int i = 0; i < 8; ++i) {
                    int cix = tid + i * 256;
                    int n = cix >> 4, ch = cix & 15;
                    uint32_t dst = sbase + SM_W + buf2*32768 + n*256
                                 + (((uint32_t)(ch ^ (n & 7))) << 4);
                    CP_ASYNC16(dst, src + ((size_t)n*DD + ch*8) * 2);
                }
                CP_COMMIT();
                CP_WAIT(1);
            } else {
                CP_WAIT(0);
            }
            __syncthreads();

            const uint32_t wBase = sbase + SM_W + (idx & 1)*32768;

            // fragment double buffers
            uint32_t aF[2][4][4];
            uint32_t bF[2][2][4];

            // load k16 = 0 fragments
            {
                const int ck  = kc*16 + aChunkOff;
                const int ck2 = bChunkOff;
#pragma unroll
                for (int mi = 0; mi < 4; ++mi)
                    ldsm_x4(aF[0][mi], aRowBase[mi] + (((uint32_t)(ck ^ aRowMask[mi])) << 4));
#pragma unroll
                for (int nj = 0; nj < 2; ++nj)
                    ldsm_x4(bF[0][nj], wBase + bRowBase[nj] + (((uint32_t)(ck2 ^ bRowMask[nj])) << 4));
            }

#pragma unroll
            for (int k16 = 0; k16 < 8; ++k16) {
                const int cur = k16 & 1, nxt = cur ^ 1;
                if (k16 < 7) {
                    const int ck  = kc*16 + (k16+1)*2 + aChunkOff;
                    const int ck2 = (k16+1)*2 + bChunkOff;
#pragma unroll
                    for (int mi = 0; mi < 4; ++mi)
                        ldsm_x4(aF[nxt][mi], aRowBase[mi] + (((uint32_t)(ck ^ aRowMask[mi])) << 4));
#pragma unroll
                    for (int nj = 0; nj < 2; ++nj)
                        ldsm_x4(bF[nxt][nj], wBase + bRowBase[nj] + (((uint32_t)(ck2 ^ bRowMask[nj])) << 4));
                }
#pragma unroll
                for (int mi = 0; mi < 4; ++mi)
#pragma unroll
                    for (int ni = 0; ni < 4; ++ni)
                        mma_bf16(acc[mi][ni], aF[cur][mi], &bF[cur][ni >> 1][(ni & 1) * 2]);
            }
            __syncthreads();
        }

        // epilogue for this n-tile
        const int colbase = nt*128 + warpN*32;
#pragma unroll
        for (int mi = 0; mi < 4; ++mi) {
            const int rowg = warpM*64 + mi*16 + g;
            const float cv0 = sCov[rowg], cv1 = sCov[rowg + 8];
#pragma unroll
            for (int ni = 0; ni < 4; ++ni) {
#pragma unroll
                for (int half = 0; half < 2; ++half) {
#pragma unroll
                    for (int jj = 0; jj < 2; ++jj) {
                        const int col = colbase + ni*8 + q*2 + jj;
                        float arg = acc[mi][ni][half*2 + jj]
                                  + sDecf[col] + (half ? cv1 : cv0) * sWc[col];
                        float t;
                        asm("tanh.approx.f32 %0, %1;" : "=f"(t) : "f"(arg));
                        rs[mi][half] += t * sV[col];
                    }
                }
            }
        }
    }

    // reduce over the 4 column-lanes (q) sharing each row, then across warpN
#pragma unroll
    for (int mi = 0; mi < 4; ++mi)
#pragma unroll
        for (int half = 0; half < 2; ++half) {
            float v = rs[mi][half];
            v += __shfl_xor_sync(0xffffffffu, v, 1);
            v += __shfl_xor_sync(0xffffffffu, v, 2);
            if (q == 0)
                atomicAdd(&sScore[warpM*64 + mi*16 + half*8 + g], v);
        }
    __syncthreads();
    if (tid < 128) g_score[row0 + tid] = sScore[tid];
}

// ============================================================
// K2: masked softmax + renormalize + coverage update, per batch.
// 1024 threads, warp-shuffle reductions.
// ============================================================
__global__ void __launch_bounds__(1024) softmax_kernel(
    const float* __restrict__ mask, const float* __restrict__ cov,
    float* __restrict__ attn_out, float* __restrict__ covnew_out)
{
    const int b = blockIdx.x, tid = threadIdx.x;
    const int lane = tid & 31, wrp = tid >> 5;
    __shared__ float red[32];
    float loc[4];
    float mx = -1e30f;
#pragma unroll
    for (int i = 0; i < 4; ++i) {
        loc[i] = g_score[b*SS + tid + i*1024];
        mx = fmaxf(mx, loc[i]);
    }
#pragma unroll
    for (int o = 16; o > 0; o >>= 1) mx = fmaxf(mx, __shfl_xor_sync(0xffffffffu, mx, o));
    if (lane == 0) red[wrp] = mx;
    __syncthreads();
    {
        float v = red[lane];
#pragma unroll
        for (int o = 16; o > 0; o >>= 1) v = fmaxf(v, __shfl_xor_sync(0xffffffffu, v, o));
        mx = v;
    }

    float sum = 0.f;
#pragma unroll
    for (int i = 0; i < 4; ++i) {
        loc[i] = expf(loc[i] - mx) * mask[b*SS + tid + i*1024];
        sum += loc[i];
    }
#pragma unroll
    for (int o = 16; o > 0; o >>= 1) sum += __shfl_xor_sync(0xffffffffu, sum, o);
    __syncthreads();
    if (lane == 0) red[wrp] = sum;
    __syncthreads();
    {
        float v = red[lane];
#pragma unroll
        for (int o = 16; o > 0; o >>= 1) v += __shfl_xor_sync(0xffffffffu, v, o);
        sum = v;
    }
    const float inv = 1.f / sum;
#pragma unroll
    for (int i = 0; i < 4; ++i) {
        int idx = b*SS + tid + i*1024;
        float a = loc[i] * inv;
        attn_out[idx]   = a;
        covnew_out[idx] = cov[idx] + a;
    }
}

// ============================================================
// K3: context partials. grid (16 s-chunks, B), 512 threads.
// Each CTA: 256 seq rows, 4 rows in flight, 128 d-threads (float4).
// ============================================================
__global__ void __launch_bounds__(512) context_kernel(
    const float* __restrict__ enc, const float* __restrict__ attn)
{
    int chunk = blockIdx.x, b = blockIdx.y, tid = threadIdx.x;
    __shared__ float sAttn[256];
    __shared__ float4 red4[512];
    if (tid < 256) sAttn[tid] = attn[b*SS + chunk*256 + tid];
    __syncthreads();
    int dt = tid & 127, sg = tid >> 7;
    float4 acc = make_float4(0.f, 0.f, 0.f, 0.f);
#pragma unroll 4
    for (int s = sg; s < 256; s += 4) {
        float a = sAttn[s];
        float4 e = *(const float4*)(enc + (size_t)(b*SS + chunk*256 + s)*DD + dt*4);
        acc.x += a*e.x; acc.y += a*e.y; acc.z += a*e.z; acc.w += a*e.w;
    }
    red4[tid] = acc; __syncthreads();
    if (sg == 0) {
        float4 r = red4[dt], r1 = red4[128+dt], r2 = red4[256+dt], r3 = red4[384+dt];
        r.x += r1.x + r2.x + r3.x; r.y += r1.y + r2.y + r3.y;
        r.z += r1.z + r2.z + r3.z; r.w += r1.w + r2.w + r3.w;
        *(float4*)(&g_ctx_part[((size_t)chunk*BB + b)*DD + dt*4]) = r;
    }
}

// K4: reduce the s-chunk partials -> context output (deterministic)
__global__ void __launch_bounds__(1024) ctx_reduce_kernel(float* __restrict__ out_ctx)
{
    int i = blockIdx.x * 1024 + threadIdx.x;  // 0..16383
    float s = 0.f;
#pragma unroll
    for (int c = 0; c < CTX_CHUNKS; ++c) s += g_ctx_part[c*(BB*DD) + i];
    out_ctx[i] = s;
}

// ============================================================
extern "C" void kernel_launch(void* const* d_in, const int* in_sizes, int n_in,
                              void* d_out, int out_size)
{
    const float* enc  = (const float*)d_in[0];
    const float* h    = (const float*)d_in[1];
    const float* c    = (const float*)d_in[2];
    const float* mask = (const float*)d_in[3];
    const float* cov  = (const float*)d_in[4];
    const float* Wh   = (const float*)d_in[5];
    const float* Ws   = (const float*)d_in[6];
    const float* Wsb  = (const float*)d_in[7];
    const float* wc   = (const float*)d_in[8];
    const float* vw   = (const float*)d_in[9];

    float* out      = (float*)d_out;
    float* out_ctx  = out;                 // (B,D)   16384
    float* out_attn = out + BB*DD;         // (B,S)   131072
    float* out_cov  = out_attn + BB*SS;    // (B,S)   131072

    cudaFuncSetAttribute(score_bf16_kernel,
                         cudaFuncAttributeMaxDynamicSharedMemorySize, SM_TOTAL);

    convert_wh_kernel<<<DD*DD/(256*8), 256>>>(Wh);
    decfeat_kernel<<<dim3(BB, 4), 128>>>(h, c, Ws, Wsb);
    score_bf16_kernel<<<MM/128, 256, SM_TOTAL>>>(enc, cov, wc, vw);
    softmax_kernel<<<BB, 1024>>>(mask, cov, out_attn, out_cov);
    context_kernel<<<dim3(CTX_CHUNKS, BB), 512>>>(enc, out_attn);
    ctx_reduce_kernel<<<(BB*DD)/1024, 1024>>>(out_ctx);
}